// round 6
// baseline (speedup 1.0000x reference)
#include <cuda_runtime.h>

// ----------------------------------------------------------------------------
// SelfAttention (SAGAN-style) fp32:
//   B=4, C=256, N=64*64=4096
//   Q[b,n,c] = sum_c' Wq[c,c'] x[b,c',n] + bq[c]   (stored (B,N,C))
//   K[b,m,c] = sum_c' Wk[c,c'] x[b,c',m] + bk[c]   (stored (B,N,C), i.e. k^T)
//   V[b,m,c] likewise (v^T)
//   E[b,n,m] = Q[b,n,:] . K[b,m,:]                 (NT GEMM)
//   A = softmax_m(E)
//   out[b,c,n] = sum_m A[b,n,m] V[b,m,c]           (NN GEMM, transposed store)
// ----------------------------------------------------------------------------

#define BB   4
#define CC   256
#define NN   4096

#define BM   128
#define BN   128
#define BK   16
#define PAD  4

// Scratch (allocation-free rule: __device__ globals)
__device__ float g_Q[(size_t)BB * NN * CC];
__device__ float g_K[(size_t)BB * NN * CC];
__device__ float g_V[(size_t)BB * NN * CC];
__device__ float g_E[(size_t)BB * NN * NN];   // energy, then attention in-place

// ============================================================================
// Kernel 1: projections.  grid (NN/BM, CC/BN, B*3), block 256
// Out[b][n][o] = sum_c W[o][c] * x[b][c][n] + bias[o]
// ============================================================================
__global__ __launch_bounds__(256, 2)
void proj_kernel(const float* __restrict__ x,
                 const float* __restrict__ Wq, const float* __restrict__ bq,
                 const float* __restrict__ Wk, const float* __restrict__ bk,
                 const float* __restrict__ Wv, const float* __restrict__ bv)
{
    __shared__ float As[BK][BM + PAD];   // As[c][n] = x[b][c][n]
    __shared__ float Bs[BK][BN + PAD];   // Bs[c][o] = W[o][c]

    const int z = blockIdx.z;
    const int b = z / 3, p = z % 3;
    const float* W    = (p == 0) ? Wq : (p == 1) ? Wk : Wv;
    const float* bias = (p == 0) ? bq : (p == 1) ? bk : bv;
    float*       Out  = (p == 0) ? g_Q : (p == 1) ? g_K : g_V;

    const int n0 = blockIdx.x * BM;
    const int o0 = blockIdx.y * BN;
    const float* xb = x + (size_t)b * CC * NN;

    const int tid = threadIdx.x;
    const int tx = tid & 15, ty = tid >> 4;

    float acc[8][8];
#pragma unroll
    for (int i = 0; i < 8; i++)
#pragma unroll
        for (int j = 0; j < 8; j++) acc[i][j] = 0.f;

    const int la_k = tid >> 5;            // 0..7  (c within tile)
    const int la_n = (tid & 31) * 4;      // 0..124 (n within tile)
    const int lb_r = tid >> 2;            // 0..63 (o row)
    const int lb_c = (tid & 3) * 4;       // 0..12 (c within tile)

    for (int c0 = 0; c0 < CC; c0 += BK) {
        // A tile: direct (n contiguous)
#pragma unroll
        for (int it = 0; it < 2; it++) {
            int k = la_k + it * 8;
            float4 v = *(const float4*)&xb[(size_t)(c0 + k) * NN + n0 + la_n];
            *(float4*)&As[k][la_n] = v;
        }
        // B tile: transpose (c contiguous in W rows)
#pragma unroll
        for (int it = 0; it < 2; it++) {
            int r = lb_r + it * 64;
            float4 v = *(const float4*)&W[(size_t)(o0 + r) * CC + c0 + lb_c];
            Bs[lb_c + 0][r] = v.x; Bs[lb_c + 1][r] = v.y;
            Bs[lb_c + 2][r] = v.z; Bs[lb_c + 3][r] = v.w;
        }
        __syncthreads();
#pragma unroll
        for (int kc = 0; kc < BK; kc++) {
            float a[8], bb2[8];
            *(float4*)&a[0]   = *(float4*)&As[kc][ty * 8];
            *(float4*)&a[4]   = *(float4*)&As[kc][ty * 8 + 4];
            *(float4*)&bb2[0] = *(float4*)&Bs[kc][tx * 8];
            *(float4*)&bb2[4] = *(float4*)&Bs[kc][tx * 8 + 4];
#pragma unroll
            for (int i = 0; i < 8; i++)
#pragma unroll
                for (int j = 0; j < 8; j++) acc[i][j] += a[i] * bb2[j];
        }
        __syncthreads();
    }

    float br[8];
#pragma unroll
    for (int j = 0; j < 8; j++) br[j] = bias[o0 + tx * 8 + j];

    float* outb = Out + (size_t)b * NN * CC;
#pragma unroll
    for (int i = 0; i < 8; i++) {
        float4 v0 = make_float4(acc[i][0] + br[0], acc[i][1] + br[1],
                                acc[i][2] + br[2], acc[i][3] + br[3]);
        float4 v1 = make_float4(acc[i][4] + br[4], acc[i][5] + br[5],
                                acc[i][6] + br[6], acc[i][7] + br[7]);
        float* dst = &outb[(size_t)(n0 + ty * 8 + i) * CC + o0 + tx * 8];
        *(float4*)&dst[0] = v0;
        *(float4*)&dst[4] = v1;
    }
}

// ============================================================================
// Kernel 2: energy NT GEMM.  grid (NN/BN, NN/BM, B), block 256
// E[b][n][m] = sum_c Q[b][n][c] * K[b][m][c]
// ============================================================================
__global__ __launch_bounds__(256, 2)
void energy_kernel()
{
    __shared__ float As[BK][BM + PAD];   // As[c][n]
    __shared__ float Bs[BK][BN + PAD];   // Bs[c][m]

    const int b  = blockIdx.z;
    const int m0 = blockIdx.x * BN;
    const int n0 = blockIdx.y * BM;
    const float* Qb = g_Q + (size_t)b * NN * CC;
    const float* Kb = g_K + (size_t)b * NN * CC;

    const int tid = threadIdx.x;
    const int tx = tid & 15, ty = tid >> 4;

    float acc[8][8];
#pragma unroll
    for (int i = 0; i < 8; i++)
#pragma unroll
        for (int j = 0; j < 8; j++) acc[i][j] = 0.f;

    const int lr = tid >> 2;            // 0..63
    const int lc = (tid & 3) * 4;       // 0..12

    for (int c0 = 0; c0 < CC; c0 += BK) {
#pragma unroll
        for (int it = 0; it < 2; it++) {
            int r = lr + it * 64;
            float4 va = *(const float4*)&Qb[(size_t)(n0 + r) * CC + c0 + lc];
            As[lc + 0][r] = va.x; As[lc + 1][r] = va.y;
            As[lc + 2][r] = va.z; As[lc + 3][r] = va.w;
            float4 vb = *(const float4*)&Kb[(size_t)(m0 + r) * CC + c0 + lc];
            Bs[lc + 0][r] = vb.x; Bs[lc + 1][r] = vb.y;
            Bs[lc + 2][r] = vb.z; Bs[lc + 3][r] = vb.w;
        }
        __syncthreads();
#pragma unroll
        for (int kc = 0; kc < BK; kc++) {
            float a[8], bb2[8];
            *(float4*)&a[0]   = *(float4*)&As[kc][ty * 8];
            *(float4*)&a[4]   = *(float4*)&As[kc][ty * 8 + 4];
            *(float4*)&bb2[0] = *(float4*)&Bs[kc][tx * 8];
            *(float4*)&bb2[4] = *(float4*)&Bs[kc][tx * 8 + 4];
#pragma unroll
            for (int i = 0; i < 8; i++)
#pragma unroll
                for (int j = 0; j < 8; j++) acc[i][j] += a[i] * bb2[j];
        }
        __syncthreads();
    }

    float* Eb = g_E + (size_t)b * NN * NN;
#pragma unroll
    for (int i = 0; i < 8; i++) {
        float* dst = &Eb[(size_t)(n0 + ty * 8 + i) * NN + m0 + tx * 8];
        *(float4*)&dst[0] = *(float4*)&acc[i][0];
        *(float4*)&dst[4] = *(float4*)&acc[i][4];
    }
}

// ============================================================================
// Kernel 3: row softmax in-place over g_E.  grid (B*NN), block 256
// ============================================================================
__device__ __forceinline__ float warpMax(float v) {
#pragma unroll
    for (int o = 16; o > 0; o >>= 1) v = fmaxf(v, __shfl_xor_sync(0xffffffffu, v, o));
    return v;
}
__device__ __forceinline__ float warpSum(float v) {
#pragma unroll
    for (int o = 16; o > 0; o >>= 1) v += __shfl_xor_sync(0xffffffffu, v, o);
    return v;
}

__global__ __launch_bounds__(256)
void softmax_kernel()
{
    __shared__ float smax[8];
    __shared__ float ssum[8];
    const size_t base = (size_t)blockIdx.x * NN;
    const int tid = threadIdx.x;
    const int lane = tid & 31, wid = tid >> 5;

    float v[16];
#pragma unroll
    for (int i = 0; i < 4; i++) {
        float4 t = *(const float4*)&g_E[base + tid * 4 + i * 1024];
        v[i * 4 + 0] = t.x; v[i * 4 + 1] = t.y; v[i * 4 + 2] = t.z; v[i * 4 + 3] = t.w;
    }

    float mx = -3.4e38f;
#pragma unroll
    for (int i = 0; i < 16; i++) mx = fmaxf(mx, v[i]);
    mx = warpMax(mx);
    if (lane == 0) smax[wid] = mx;
    __syncthreads();
    if (wid == 0) {
        float t = (lane < 8) ? smax[lane] : -3.4e38f;
        t = warpMax(t);
        if (lane == 0) smax[0] = t;
    }
    __syncthreads();
    mx = smax[0];

    float s = 0.f;
#pragma unroll
    for (int i = 0; i < 16; i++) { v[i] = expf(v[i] - mx); s += v[i]; }
    s = warpSum(s);
    if (lane == 0) ssum[wid] = s;
    __syncthreads();
    if (wid == 0) {
        float t = (lane < 8) ? ssum[lane] : 0.f;
        t = warpSum(t);
        if (lane == 0) ssum[0] = t;
    }
    __syncthreads();
    const float inv = 1.0f / ssum[0];

#pragma unroll
    for (int i = 0; i < 4; i++) {
        float4 t = make_float4(v[i * 4 + 0] * inv, v[i * 4 + 1] * inv,
                               v[i * 4 + 2] * inv, v[i * 4 + 3] * inv);
        *(float4*)&g_E[base + tid * 4 + i * 1024] = t;
    }
}

// ============================================================================
// Kernel 4: out NN GEMM + transposed store.  grid (CC/BN, NN/BM, B), block 256
// O[b][n][o] = sum_m A[b][n][m] * V[b][m][o];  d_out[b][o][n] = O[b][n][o]
// ============================================================================
__global__ __launch_bounds__(256, 2)
void av_kernel(float* __restrict__ out)
{
    __shared__ float As[BK][BM + PAD];   // As[m][n] = A[n][m]
    __shared__ float Bs[BK][BN + PAD];   // Bs[m][o] = V[m][o]

    const int b  = blockIdx.z;
    const int o0 = blockIdx.x * BN;
    const int n0 = blockIdx.y * BM;
    const float* Ab = g_E + (size_t)b * NN * NN;
    const float* Vb = g_V + (size_t)b * NN * CC;

    const int tid = threadIdx.x;
    const int tx = tid & 15, ty = tid >> 4;

    float acc[8][8];
#pragma unroll
    for (int i = 0; i < 8; i++)
#pragma unroll
        for (int j = 0; j < 8; j++) acc[i][j] = 0.f;

    const int la_r = tid >> 2;            // 0..63  (n row, transpose load of A)
    const int la_c = (tid & 3) * 4;       // 0..12  (m within tile)
    const int lb_k = tid >> 5;            // 0..7   (m within tile, direct V load)
    const int lb_o = (tid & 31) * 4;      // 0..124 (o)

    for (int m0 = 0; m0 < NN; m0 += BK) {
#pragma unroll
        for (int it = 0; it < 2; it++) {
            int r = la_r + it * 64;
            float4 va = *(const float4*)&Ab[(size_t)(n0 + r) * NN + m0 + la_c];
            As[la_c + 0][r] = va.x; As[la_c + 1][r] = va.y;
            As[la_c + 2][r] = va.z; As[la_c + 3][r] = va.w;
        }
#pragma unroll
        for (int it = 0; it < 2; it++) {
            int k = lb_k + it * 8;
            float4 vb = *(const float4*)&Vb[(size_t)(m0 + k) * CC + o0 + lb_o];
            *(float4*)&Bs[k][lb_o] = vb;
        }
        __syncthreads();
#pragma unroll
        for (int kc = 0; kc < BK; kc++) {
            float a[8], bb2[8];
            *(float4*)&a[0]   = *(float4*)&As[kc][ty * 8];
            *(float4*)&a[4]   = *(float4*)&As[kc][ty * 8 + 4];
            *(float4*)&bb2[0] = *(float4*)&Bs[kc][tx * 8];
            *(float4*)&bb2[4] = *(float4*)&Bs[kc][tx * 8 + 4];
#pragma unroll
            for (int i = 0; i < 8; i++)
#pragma unroll
                for (int j = 0; j < 8; j++) acc[i][j] += a[i] * bb2[j];
        }
        __syncthreads();
    }

    // transposed store: out[b][o][n], n contiguous per thread (8 floats)
#pragma unroll
    for (int j = 0; j < 8; j++) {
        float4 w0 = make_float4(acc[0][j], acc[1][j], acc[2][j], acc[3][j]);
        float4 w1 = make_float4(acc[4][j], acc[5][j], acc[6][j], acc[7][j]);
        float* dst = out + ((size_t)b * CC + o0 + tx * 8 + j) * NN + n0 + ty * 8;
        *(float4*)&dst[0] = w0;
        *(float4*)&dst[4] = w1;
    }
}

// ============================================================================
extern "C" void kernel_launch(void* const* d_in, const int* in_sizes, int n_in,
                              void* d_out, int out_size)
{
    const float* x  = (const float*)d_in[0];
    const float* Wq = (const float*)d_in[1];
    const float* bq = (const float*)d_in[2];
    const float* Wk = (const float*)d_in[3];
    const float* bk = (const float*)d_in[4];
    const float* Wv = (const float*)d_in[5];
    const float* bv = (const float*)d_in[6];
    float* out = (float*)d_out;

    dim3 blk(256);
    dim3 gproj(NN / BM, CC / BN, BB * 3);      // 32 x 2 x 12
    proj_kernel<<<gproj, blk>>>(x, Wq, bq, Wk, bk, Wv, bv);

    dim3 genergy(NN / BN, NN / BM, BB);        // 32 x 32 x 4
    energy_kernel<<<genergy, blk>>>();

    softmax_kernel<<<BB * NN, blk>>>();        // 16384 rows

    dim3 gav(CC / BN, NN / BM, BB);            // 2 x 32 x 4
    av_kernel<<<gav, blk>>>(out);
}

// round 10
// speedup vs baseline: 2.3516x; 2.3516x over previous
#include <cuda_runtime.h>
#include <cuda_bf16.h>
#include <cstdint>

// ----------------------------------------------------------------------------
// SelfAttention (SAGAN-style), B=4, C=256, N=4096.
// mma.sync bf16 split-GEMM (hi/lo, K x3) for energy and A*V; fp32 elsewhere.
// ----------------------------------------------------------------------------

#define BB   4
#define CC   256
#define NT   4096

// ---------------- scratch (__device__ globals; no allocation) ---------------
__device__ __nv_bfloat16 g_Qs[(size_t)BB * NT * 512];      // [b][n][hi 256 | lo 256]
__device__ __nv_bfloat16 g_Ks[(size_t)BB * NT * 512];      // [b][m][hi 256 | lo 256]
__device__ __nv_bfloat16 g_Vt[(size_t)BB * CC * 8192];     // [b][o][hi 4096 | lo 4096]
__device__ __nv_bfloat16 g_As[(size_t)BB * NT * 8192];     // [b][n][hi 4096 | lo 4096]
__device__ float         g_E [(size_t)BB * NT * NT];       // energy fp32

// ---------------- helpers ----------------------------------------------------
__device__ __forceinline__ uint32_t smem_u32(const void* p) {
    uint32_t a;
    asm("{ .reg .u64 t; cvta.to.shared.u64 t, %1; cvt.u32.u64 %0, t; }"
        : "=r"(a) : "l"(p));
    return a;
}
__device__ __forceinline__ void cp_async16(uint32_t dst, const void* src) {
    asm volatile("cp.async.cg.shared.global [%0], [%1], 16;" :: "r"(dst), "l"(src));
}
__device__ __forceinline__ void cp_commit() {
    asm volatile("cp.async.commit_group;" ::: "memory");
}
template <int N>
__device__ __forceinline__ void cp_wait() {
    asm volatile("cp.async.wait_group %0;" :: "n"(N) : "memory");
}
__device__ __forceinline__ void ldm_x4(uint32_t& r0, uint32_t& r1,
                                       uint32_t& r2, uint32_t& r3, uint32_t addr) {
    asm volatile("ldmatrix.sync.aligned.m8n8.x4.shared.b16 {%0,%1,%2,%3}, [%4];"
        : "=r"(r0), "=r"(r1), "=r"(r2), "=r"(r3) : "r"(addr));
}
__device__ __forceinline__ void mma16816(float* d, const uint32_t* a, const uint32_t* b) {
    asm volatile(
        "mma.sync.aligned.m16n8k16.row.col.f32.bf16.bf16.f32 "
        "{%0,%1,%2,%3}, {%4,%5,%6,%7}, {%8,%9}, {%0,%1,%2,%3};"
        : "+f"(d[0]), "+f"(d[1]), "+f"(d[2]), "+f"(d[3])
        : "r"(a[0]), "r"(a[1]), "r"(a[2]), "r"(a[3]), "r"(b[0]), "r"(b[1]));
}
#define SWZ(o) ((o) ^ (((o) >> 3) & 0x70))

__device__ __forceinline__ void split_bf16(float v, __nv_bfloat16& h, __nv_bfloat16& l) {
    h = __float2bfloat16(v);
    l = __float2bfloat16(v - __bfloat162float(h));
}

// ---------------- GEMM mainloop config --------------------------------------
#define STAGES      3
#define CHUNK       64                 // bf16 K per chunk (128B rows, SW128)
#define TILE_BYTES  16384              // 128 rows * 128B
#define STAGE_BYTES (2 * TILE_BYTES)
#define SM_GEMM     (STAGES * STAGE_BYTES)     // 96KB
#define SM_TS       (128 * 132 * 4)            // 67.6KB transpose scratch (AV)
#define SM_TOTAL    (SM_GEMM > SM_TS ? SM_GEMM : SM_TS)

// C[128n x 128o] = sum over 3 streams of A[row][k] * B[row][k] (both K-contig).
// Streams: A = {hi, hi, lo}, B = {hi, lo, hi}. nsc = chunks per stream.
// Chunk c lives in buffer (c % STAGES); chunk c+2 is prefetched into buffer
// ((c+2) % STAGES) after computing chunk c (that buffer was last read at
// iteration c-1, protected by the top-of-loop barrier of iteration c).
__device__ __forceinline__ void gemm_mainloop(
    char* smem, float acc[2][8][4],
    const __nv_bfloat16* __restrict__ aBase, int aStride, int loA,
    const __nv_bfloat16* __restrict__ bBase, int bStride, int loB, int nsc)
{
    const int tid  = threadIdx.x;
    const int wid  = tid >> 5, lane = tid & 31;
    const int wm   = wid >> 1, wn = wid & 1;
    const int nch  = 3 * nsc;
    const uint32_t sb = smem_u32(smem);

    // static ldmatrix address components
    const int arow  = wm * 32 + (lane & 15);
    const int acolb = (lane >> 4) * 16;
    const int brow  = wn * 64 + ((lane >> 4) << 3) + (lane & 7);
    const int bcolb = ((lane >> 3) & 1) * 16;

#define LOAD_CHUNK(c, stg) do {                                                  \
        int _st = (c) / nsc;                                                     \
        int _kf = ((c) % nsc) * CHUNK;                                           \
        int _ao = (_st == 2 ? loA : 0) + _kf;                                    \
        int _bo = (_st == 1 ? loB : 0) + _kf;                                    \
        uint32_t _ab = sb + (stg) * STAGE_BYTES;                                 \
        uint32_t _bb = _ab + TILE_BYTES;                                         \
        _Pragma("unroll")                                                        \
        for (int _p = 0; _p < 4; _p++) {                                         \
            int _idx = tid + _p * 256;                                           \
            int _row = _idx >> 3, _ch = _idx & 7;                                \
            uint32_t _so = SWZ(_row * 128 + _ch * 16);                           \
            cp_async16(_ab + _so, aBase + (size_t)_row * aStride + _ao + _ch * 8); \
            cp_async16(_bb + _so, bBase + (size_t)_row * bStride + _bo + _ch * 8); \
        }                                                                        \
        cp_commit();                                                             \
    } while (0)

#pragma unroll
    for (int s = 0; s < STAGES - 1; s++) LOAD_CHUNK(s, s);

    int cur = 0, nxt = STAGES - 1;
    for (int c = 0; c < nch; c++) {
        // Last iteration has only its own group outstanding: must wait fully.
        if (c < nch - 1) cp_wait<STAGES - 2>();
        else             cp_wait<0>();
        __syncthreads();
        const uint32_t abase = sb + cur * STAGE_BYTES;
        const uint32_t bbase = abase + TILE_BYTES;
#pragma unroll
        for (int ki = 0; ki < 4; ki++) {
            uint32_t af[2][4], bf[4][4];
#pragma unroll
            for (int mi = 0; mi < 2; mi++)
                ldm_x4(af[mi][0], af[mi][1], af[mi][2], af[mi][3],
                       abase + SWZ((arow + mi * 16) * 128 + ki * 32 + acolb));
#pragma unroll
            for (int nj = 0; nj < 4; nj++)
                ldm_x4(bf[nj][0], bf[nj][1], bf[nj][2], bf[nj][3],
                       bbase + SWZ((brow + nj * 16) * 128 + ki * 32 + bcolb));
#pragma unroll
            for (int mi = 0; mi < 2; mi++)
#pragma unroll
                for (int nj = 0; nj < 4; nj++) {
                    mma16816(acc[mi][nj * 2 + 0], af[mi], &bf[nj][0]);
                    mma16816(acc[mi][nj * 2 + 1], af[mi], &bf[nj][2]);
                }
        }
        if (c + STAGES - 1 < nch) LOAD_CHUNK(c + STAGES - 1, nxt);
        cur = (cur + 1 == STAGES) ? 0 : cur + 1;
        nxt = (nxt + 1 == STAGES) ? 0 : nxt + 1;
    }
#undef LOAD_CHUNK
}

// ============================================================================
// Kernel 1: projections (fp32 SIMT) -> split bf16 outputs.
// grid (NT/128, CC/128, B*3), block 256
// ============================================================================
__global__ __launch_bounds__(256, 2)
void proj_kernel(const float* __restrict__ x,
                 const float* __restrict__ Wq, const float* __restrict__ bq,
                 const float* __restrict__ Wk, const float* __restrict__ bk,
                 const float* __restrict__ Wv, const float* __restrict__ bv)
{
    __shared__ float As[16][132];
    __shared__ float Bs[16][132];

    const int z = blockIdx.z;
    const int b = z / 3, p = z % 3;
    const float* W    = (p == 0) ? Wq : (p == 1) ? Wk : Wv;
    const float* bias = (p == 0) ? bq : (p == 1) ? bk : bv;

    const int n0 = blockIdx.x * 128;
    const int o0 = blockIdx.y * 128;
    const float* xb = x + (size_t)b * CC * NT;

    const int tid = threadIdx.x;
    const int tx = tid & 15, ty = tid >> 4;

    float acc[8][8];
#pragma unroll
    for (int i = 0; i < 8; i++)
#pragma unroll
        for (int j = 0; j < 8; j++) acc[i][j] = 0.f;

    const int la_k = tid >> 5;
    const int la_n = (tid & 31) * 4;
    const int lb_r = tid >> 2;
    const int lb_c = (tid & 3) * 4;

    for (int c0 = 0; c0 < CC; c0 += 16) {
#pragma unroll
        for (int it = 0; it < 2; it++) {
            int k = la_k + it * 8;
            float4 v = *(const float4*)&xb[(size_t)(c0 + k) * NT + n0 + la_n];
            *(float4*)&As[k][la_n] = v;
        }
#pragma unroll
        for (int it = 0; it < 2; it++) {
            int r = lb_r + it * 64;
            float4 v = *(const float4*)&W[(size_t)(o0 + r) * CC + c0 + lb_c];
            Bs[lb_c + 0][r] = v.x; Bs[lb_c + 1][r] = v.y;
            Bs[lb_c + 2][r] = v.z; Bs[lb_c + 3][r] = v.w;
        }
        __syncthreads();
#pragma unroll
        for (int kc = 0; kc < 16; kc++) {
            float a[8], bb2[8];
            *(float4*)&a[0]   = *(float4*)&As[kc][ty * 8];
            *(float4*)&a[4]   = *(float4*)&As[kc][ty * 8 + 4];
            *(float4*)&bb2[0] = *(float4*)&Bs[kc][tx * 8];
            *(float4*)&bb2[4] = *(float4*)&Bs[kc][tx * 8 + 4];
#pragma unroll
            for (int i = 0; i < 8; i++)
#pragma unroll
                for (int j = 0; j < 8; j++) acc[i][j] += a[i] * bb2[j];
        }
        __syncthreads();
    }

    float br[8];
#pragma unroll
    for (int j = 0; j < 8; j++) br[j] = bias[o0 + tx * 8 + j];

    if (p < 2) {
        __nv_bfloat16* Out = (p == 0) ? g_Qs : g_Ks;
#pragma unroll
        for (int i = 0; i < 8; i++) {
            __nv_bfloat16 h8[8], l8[8];
#pragma unroll
            for (int j = 0; j < 8; j++) split_bf16(acc[i][j] + br[j], h8[j], l8[j]);
            __nv_bfloat16* dst = Out + ((size_t)(b * NT + n0 + ty * 8 + i)) * 512 + o0 + tx * 8;
            *(uint4*)dst         = *(uint4*)h8;
            *(uint4*)(dst + 256) = *(uint4*)l8;
        }
    } else {
#pragma unroll
        for (int j = 0; j < 8; j++) {
            __nv_bfloat16 h8[8], l8[8];
#pragma unroll
            for (int i = 0; i < 8; i++) split_bf16(acc[i][j] + br[j], h8[i], l8[i]);
            __nv_bfloat16* dst = g_Vt + ((size_t)(b * CC + o0 + tx * 8 + j)) * 8192 + n0 + ty * 8;
            *(uint4*)dst          = *(uint4*)h8;
            *(uint4*)(dst + 4096) = *(uint4*)l8;
        }
    }
}

// ============================================================================
// Kernel 2: energy E[b][n][m].  grid (32 m, 32 n, B), block 256
// ============================================================================
__global__ __launch_bounds__(256)
void energy_mma_kernel()
{
    extern __shared__ char smem[];
    const int b = blockIdx.z, m0 = blockIdx.x * 128, n0 = blockIdx.y * 128;
    const int wid = threadIdx.x >> 5, lane = threadIdx.x & 31;
    const int wm = wid >> 1, wn = wid & 1;

    float acc[2][8][4];
#pragma unroll
    for (int mi = 0; mi < 2; mi++)
#pragma unroll
        for (int j = 0; j < 8; j++)
#pragma unroll
            for (int k = 0; k < 4; k++) acc[mi][j][k] = 0.f;

    gemm_mainloop(smem, acc,
                  g_Qs + (size_t)(b * NT + n0) * 512, 512, 256,
                  g_Ks + (size_t)(b * NT + m0) * 512, 512, 256, 4);

    float* Eb = g_E + (size_t)b * NT * NT;
#pragma unroll
    for (int mi = 0; mi < 2; mi++) {
        int r = n0 + wm * 32 + mi * 16 + (lane >> 2);
#pragma unroll
        for (int j = 0; j < 8; j++) {
            int cm = m0 + wn * 64 + j * 8 + (lane & 3) * 2;
            *(float2*)&Eb[(size_t)r * NT + cm]       = make_float2(acc[mi][j][0], acc[mi][j][1]);
            *(float2*)&Eb[(size_t)(r + 8) * NT + cm] = make_float2(acc[mi][j][2], acc[mi][j][3]);
        }
    }
}

// ============================================================================
// Kernel 3: row softmax fp32 -> split-bf16 attention.  grid (B*NT), block 256
// ============================================================================
__device__ __forceinline__ float warpMax(float v) {
#pragma unroll
    for (int o = 16; o > 0; o >>= 1) v = fmaxf(v, __shfl_xor_sync(0xffffffffu, v, o));
    return v;
}
__device__ __forceinline__ float warpSum(float v) {
#pragma unroll
    for (int o = 16; o > 0; o >>= 1) v += __shfl_xor_sync(0xffffffffu, v, o);
    return v;
}

__global__ __launch_bounds__(256)
void softmax_kernel()
{
    __shared__ float sred[8];
    const size_t row = blockIdx.x;
    const int tid = threadIdx.x;
    const int lane = tid & 31, wid = tid >> 5;

    float v[16];
#pragma unroll
    for (int i = 0; i < 4; i++) {
        float4 t = *(const float4*)&g_E[row * NT + tid * 4 + i * 1024];
        v[i * 4 + 0] = t.x; v[i * 4 + 1] = t.y; v[i * 4 + 2] = t.z; v[i * 4 + 3] = t.w;
    }

    float mx = -3.4e38f;
#pragma unroll
    for (int i = 0; i < 16; i++) mx = fmaxf(mx, v[i]);
    mx = warpMax(mx);
    if (lane == 0) sred[wid] = mx;
    __syncthreads();
    if (wid == 0) {
        float t = (lane < 8) ? sred[lane] : -3.4e38f;
        t = warpMax(t);
        if (lane == 0) sred[0] = t;
    }
    __syncthreads();
    mx = sred[0];
    __syncthreads();

    float s = 0.f;
#pragma unroll
    for (int i = 0; i < 16; i++) { v[i] = __expf(v[i] - mx); s += v[i]; }
    s = warpSum(s);
    if (lane == 0) sred[wid] = s;
    __syncthreads();
    if (wid == 0) {
        float t = (lane < 8) ? sred[lane] : 0.f;
        t = warpSum(t);
        if (lane == 0) sred[0] = t;
    }
    __syncthreads();
    const float inv = 1.0f / sred[0];

    __nv_bfloat16* arow = g_As + row * 8192;
#pragma unroll
    for (int i = 0; i < 4; i++) {
        __nv_bfloat16 h4[4], l4[4];
#pragma unroll
        for (int k = 0; k < 4; k++) split_bf16(v[i * 4 + k] * inv, h4[k], l4[k]);
        int m = tid * 4 + i * 1024;
        *(uint2*)(arow + m)        = *(uint2*)h4;
        *(uint2*)(arow + 4096 + m) = *(uint2*)l4;
    }
}

// ============================================================================
// Kernel 4: out[b][o][n] = sum_m A[n][m] V[m][o].  grid (2 o, 32 n, B), 256
// ============================================================================
__global__ __launch_bounds__(256)
void av_mma_kernel(float* __restrict__ out)
{
    extern __shared__ char smem[];
    const int b = blockIdx.z, o0 = blockIdx.x * 128, n0 = blockIdx.y * 128;
    const int tid = threadIdx.x;
    const int wid = tid >> 5, lane = tid & 31;
    const int wm = wid >> 1, wn = wid & 1;

    float acc[2][8][4];
#pragma unroll
    for (int mi = 0; mi < 2; mi++)
#pragma unroll
        for (int j = 0; j < 8; j++)
#pragma unroll
            for (int k = 0; k < 4; k++) acc[mi][j][k] = 0.f;

    gemm_mainloop(smem, acc,
                  g_As + (size_t)(b * NT + n0) * 8192, 8192, 4096,
                  g_Vt + (size_t)(b * CC + o0) * 8192, 8192, 4096, 64);

    // transpose C[n][o] -> out[b][o][n] via smem (reuse pipeline buffers)
    float* ts = (float*)smem;                  // [128 n][132]
    __syncthreads();
#pragma unroll
    for (int mi = 0; mi < 2; mi++) {
        int r = wm * 32 + mi * 16 + (lane >> 2);
#pragma unroll
        for (int j = 0; j < 8; j++) {
            int o = wn * 64 + j * 8 + (lane & 3) * 2;
            *(float2*)&ts[(size_t)r * 132 + o]       = make_float2(acc[mi][j][0], acc[mi][j][1]);
            *(float2*)&ts[(size_t)(r + 8) * 132 + o] = make_float2(acc[mi][j][2], acc[mi][j][3]);
        }
    }
    __syncthreads();

    const int o = tid >> 1;
    const int nh = (tid & 1) * 64;
    float* dst = out + ((size_t)(b * CC + o0 + o)) * NT + n0 + nh;
#pragma unroll
    for (int g = 0; g < 16; g++) {
        int n = nh + g * 4;
        float4 v = make_float4(ts[(n + 0) * 132 + o], ts[(n + 1) * 132 + o],
                               ts[(n + 2) * 132 + o], ts[(n + 3) * 132 + o]);
        *(float4*)(dst + g * 4) = v;
    }
}

// ============================================================================
extern "C" void kernel_launch(void* const* d_in, const int* in_sizes, int n_in,
                              void* d_out, int out_size)
{
    const float* x  = (const float*)d_in[0];
    const float* Wq = (const float*)d_in[1];
    const float* bq = (const float*)d_in[2];
    const float* Wk = (const float*)d_in[3];
    const float* bk = (const float*)d_in[4];
    const float* Wv = (const float*)d_in[5];
    const float* bv = (const float*)d_in[6];
    float* out = (float*)d_out;

    cudaFuncSetAttribute(energy_mma_kernel,
                         cudaFuncAttributeMaxDynamicSharedMemorySize, SM_TOTAL);
    cudaFuncSetAttribute(av_mma_kernel,
                         cudaFuncAttributeMaxDynamicSharedMemorySize, SM_TOTAL);

    dim3 gproj(NT / 128, CC / 128, BB * 3);
    proj_kernel<<<gproj, 256>>>(x, Wq, bq, Wk, bk, Wv, bv);

    dim3 gen(NT / 128, NT / 128, BB);          // 32 x 32 x 4
    energy_mma_kernel<<<gen, 256, SM_TOTAL>>>();

    softmax_kernel<<<BB * NT, 256>>>();

    dim3 gav(CC / 128, NT / 128, BB);          // 2 x 32 x 4
    av_mma_kernel<<<gav, 256, SM_TOTAL>>>(out);
}